// round 16
// baseline (speedup 1.0000x reference)
#include <cuda_runtime.h>
#include <cuda_bf16.h>
#include <math.h>
#include <stdint.h>

#define T_   2048
#define B_   8
#define S_   512
#define D_   512
#define H_   8
#define DH   64
#define DFF_ 2048
#define NQ_  10
#define W_   16
#define NW   128
#define EPS  1e-5f
#define NEGV -1e30f

// ---------------- scratch ----------------
__device__ float g_qn[NQ_ * D_];
__device__ float g_sc[T_ * B_ * NQ_];
__device__ float g_qa[B_ * NW * D_];
__device__ float g_x1[T_ * B_ * D_];
__device__ float g_q [T_ * B_ * D_];
__device__ float g_kv[S_ * B_ * 2 * D_];
__device__ float g_tmp[T_ * B_ * D_];
__device__ float g_x2[T_ * B_ * D_];

__device__ __nv_bfloat16 g_x1h[T_ * B_ * D_], g_x1l[T_ * B_ * D_];
__device__ __nv_bfloat16 g_x2h[T_ * B_ * D_], g_x2l[T_ * B_ * D_];
__device__ __nv_bfloat16 g_obh[T_ * B_ * D_], g_obl[T_ * B_ * D_];
__device__ __nv_bfloat16 g_hh [T_ * B_ * DFF_], g_hl [T_ * B_ * DFF_];
__device__ __nv_bfloat16 g_memh[S_ * B_ * D_], g_meml[S_ * B_ * D_];
#define WOFF_IN  0
#define WOFF_OUT (1536 * 512)
#define WOFF_L1  (WOFF_OUT + 512 * 512)
#define WOFF_L2  (WOFF_L1 + 2048 * 512)
#define WTOT     (WOFF_L2 + 512 * 2048)
__device__ __nv_bfloat16 g_wh[WTOT], g_wl[WTOT];

// ---------------- helpers ----------------
__device__ __forceinline__ uint32_t smem_u32(const void* p) {
    uint32_t a;
    asm("{ .reg .u64 t; cvta.to.shared.u64 t, %1; cvt.u32.u64 %0, t; }" : "=r"(a) : "l"(p));
    return a;
}
__device__ __forceinline__ void split1(float a, __nv_bfloat16& h, __nv_bfloat16& l) {
    h = __float2bfloat16(a);
    l = __float2bfloat16(a - __bfloat162float(h));
}
__device__ __forceinline__ void ldsm4(uint32_t* r, uint32_t addr) {
    asm volatile("ldmatrix.sync.aligned.m8n8.x4.shared.b16 {%0,%1,%2,%3}, [%4];"
        : "=r"(r[0]), "=r"(r[1]), "=r"(r[2]), "=r"(r[3]) : "r"(addr));
}
__device__ __forceinline__ void ldsm4t(uint32_t* r, uint32_t addr) {
    asm volatile("ldmatrix.sync.aligned.m8n8.x4.trans.shared.b16 {%0,%1,%2,%3}, [%4];"
        : "=r"(r[0]), "=r"(r[1]), "=r"(r[2]), "=r"(r[3]) : "r"(addr));
}
__device__ __forceinline__ void mma_bf16(float* d, const uint32_t* a, uint32_t b0, uint32_t b1) {
    asm("mma.sync.aligned.m16n8k16.row.col.f32.bf16.bf16.f32 "
        "{%0,%1,%2,%3}, {%4,%5,%6,%7}, {%8,%9}, {%0,%1,%2,%3};"
        : "+f"(d[0]), "+f"(d[1]), "+f"(d[2]), "+f"(d[3])
        : "r"(a[0]), "r"(a[1]), "r"(a[2]), "r"(a[3]), "r"(b0), "r"(b1));
}
__device__ __forceinline__ void cpa16(uint32_t d, const void* s) {
    asm volatile("cp.async.cg.shared.global [%0], [%1], 16;" :: "r"(d), "l"(s));
}
#define CP_COMMIT() asm volatile("cp.async.commit_group;")
#define CP_WAIT1()  asm volatile("cp.async.wait_group 1;")

#define MMA12(ACC, AH, AL, B0H, B1H, B0L, B1L) do {      \
    mma_bf16(ACC[0], AH, B0H[0], B0H[1]);                \
    mma_bf16(ACC[1], AH, B0H[2], B0H[3]);                \
    mma_bf16(ACC[2], AH, B1H[0], B1H[1]);                \
    mma_bf16(ACC[3], AH, B1H[2], B1H[3]);                \
    mma_bf16(ACC[0], AH, B0L[0], B0L[1]);                \
    mma_bf16(ACC[1], AH, B0L[2], B0L[3]);                \
    mma_bf16(ACC[2], AH, B1L[0], B1L[1]);                \
    mma_bf16(ACC[3], AH, B1L[2], B1L[3]);                \
    mma_bf16(ACC[0], AL, B0H[0], B0H[1]);                \
    mma_bf16(ACC[1], AL, B0H[2], B0H[3]);                \
    mma_bf16(ACC[2], AL, B1H[0], B1H[1]);                \
    mma_bf16(ACC[3], AL, B1H[2], B1H[3]);                \
} while (0)

// ---------------- fused fp32 -> bf16 hi/lo split ----------------
__device__ __forceinline__ void split4_store(float4 v, __nv_bfloat162* dh, __nv_bfloat162* dl, int j) {
    __nv_bfloat16 hx, lx, hy, ly, hz, lz, hw, lw;
    split1(v.x, hx, lx); split1(v.y, hy, ly);
    split1(v.z, hz, lz); split1(v.w, hw, lw);
    dh[2 * j]     = __nv_bfloat162(hx, hy);
    dh[2 * j + 1] = __nv_bfloat162(hz, hw);
    dl[2 * j]     = __nv_bfloat162(lx, ly);
    dl[2 * j + 1] = __nv_bfloat162(lz, lw);
}

__global__ void split_all_kernel(const float4* __restrict__ inw, const float4* __restrict__ outw,
                                 const float4* __restrict__ l1w, const float4* __restrict__ l2w,
                                 const float4* __restrict__ mem,
                                 __nv_bfloat16* __restrict__ wh, __nv_bfloat16* __restrict__ wl,
                                 __nv_bfloat16* __restrict__ memh, __nv_bfloat16* __restrict__ meml) {
    int i = blockIdx.x * 256 + threadIdx.x;
    const int n0 = 1536 * 512 / 4;
    const int n1 = n0 + 512 * 512 / 4;
    const int n2 = n1 + 2048 * 512 / 4;
    const int n3 = n2 + 512 * 2048 / 4;
    const int n4 = n3 + S_ * B_ * D_ / 4;
    if (i >= n4) return;
    const float4* src; __nv_bfloat162 *dh, *dl; int j;
    if (i < n0)      { j = i;      src = inw;  dh = (__nv_bfloat162*)(wh + WOFF_IN);  dl = (__nv_bfloat162*)(wl + WOFF_IN); }
    else if (i < n1) { j = i - n0; src = outw; dh = (__nv_bfloat162*)(wh + WOFF_OUT); dl = (__nv_bfloat162*)(wl + WOFF_OUT); }
    else if (i < n2) { j = i - n1; src = l1w;  dh = (__nv_bfloat162*)(wh + WOFF_L1);  dl = (__nv_bfloat162*)(wl + WOFF_L1); }
    else if (i < n3) { j = i - n2; src = l2w;  dh = (__nv_bfloat162*)(wh + WOFF_L2);  dl = (__nv_bfloat162*)(wl + WOFF_L2); }
    else             { j = i - n3; src = mem;  dh = (__nv_bfloat162*)memh;            dl = (__nv_bfloat162*)meml; }
    split4_store(src[j], dh, dl, j);
}

// ================= HMMA GEMM: 512 thr / 16 warps, warp tile 32x32 =================
#define STG_ELEM (128 * 40)
#define STG_BYTE (STG_ELEM * 2)
#define GT_SMEM  (8 * STG_BYTE)

template<int RELU, int OSPLIT>
__global__ __launch_bounds__(512, 2) void gemm_bf16_v2(
    const __nv_bfloat16* __restrict__ Ah, const __nv_bfloat16* __restrict__ Al,
    const __nv_bfloat16* __restrict__ Bh, const __nv_bfloat16* __restrict__ Bl,
    const float* __restrict__ bias, float* __restrict__ C,
    __nv_bfloat16* __restrict__ Ch, __nv_bfloat16* __restrict__ Cl,
    int M, int N, int K)
{
    extern __shared__ __nv_bfloat16 dsm[];
    __nv_bfloat16* sAh = dsm;
    __nv_bfloat16* sAl = dsm + 2 * STG_ELEM;
    __nv_bfloat16* sBh = dsm + 4 * STG_ELEM;
    __nv_bfloat16* sBl = dsm + 6 * STG_ELEM;

    int tid = threadIdx.x, lane = tid & 31, wid = tid >> 5;
    int m0 = blockIdx.y * 128, n0 = blockIdx.x * 128;
    int warp_m = wid >> 2, warp_n = wid & 3;

    float acc[2][4][4];
    #pragma unroll
    for (int i = 0; i < 2; i++)
        #pragma unroll
        for (int j = 0; j < 4; j++)
            #pragma unroll
            for (int k = 0; k < 4; k++) acc[i][j][k] = 0.f;

    uint32_t uAh = smem_u32(sAh), uAl = smem_u32(sAl);
    uint32_t uBh = smem_u32(sBh), uBl = smem_u32(sBl);

    uint32_t a_off = ((warp_m * 32 + (lane & 15)) * 40 + (lane >> 4) * 8) * 2;
    uint32_t b_off = ((warp_n * 32 + ((lane >> 4) & 1) * 8 + (lane & 7)) * 40
                      + ((lane >> 3) & 1) * 8) * 2;

    int lrow = tid >> 2;
    int lp   = (tid & 3) * 8;
    uint32_t sdst = (lrow * 40 + lp) * 2;
    const __nv_bfloat16* Arow  = Ah + (size_t)(m0 + lrow) * K + lp;
    const __nv_bfloat16* Alrow = Al + (size_t)(m0 + lrow) * K + lp;
    const __nv_bfloat16* Brow  = Bh + (size_t)(n0 + lrow) * K + lp;
    const __nv_bfloat16* Blrow = Bl + (size_t)(n0 + lrow) * K + lp;

    auto prefetch = [&](int kc, int st) {
        uint32_t so = st * STG_BYTE + sdst;
        cpa16(uAh + so, Arow + kc);
        cpa16(uAl + so, Alrow + kc);
        cpa16(uBh + so, Brow + kc);
        cpa16(uBl + so, Blrow + kc);
        CP_COMMIT();
    };

    int nch = K >> 5;
    prefetch(0, 0);
    prefetch(32, 1);

    for (int c = 0; c < nch; c++) {
        CP_WAIT1();
        __syncthreads();
        uint32_t stb = (c & 1) * STG_BYTE;
        #pragma unroll
        for (int ks = 0; ks < 2; ks++) {
            uint32_t b0h[4], b1h[4], b0l[4], b1l[4];
            ldsm4(b0h, uBh + stb + b_off + ks * 32);
            ldsm4(b1h, uBh + stb + b_off + 1280 + ks * 32);
            ldsm4(b0l, uBl + stb + b_off + ks * 32);
            ldsm4(b1l, uBl + stb + b_off + 1280 + ks * 32);
            #pragma unroll
            for (int mi = 0; mi < 2; mi++) {
                uint32_t ah[4], al[4];
                ldsm4(ah, uAh + stb + a_off + mi * 1280 + ks * 32);
                ldsm4(al, uAl + stb + a_off + mi * 1280 + ks * 32);
                MMA12(acc[mi], ah, al, b0h, b1h, b0l, b1l);
            }
        }
        __syncthreads();
        int nk = c + 2;
        if (nk < nch) prefetch(nk << 5, nk & 1);
    }

    int r0 = lane >> 2, c0 = (lane & 3) * 2;
    int mbase = m0 + warp_m * 32, nbase = n0 + warp_n * 32;
    #pragma unroll
    for (int mi = 0; mi < 2; mi++) {
        #pragma unroll
        for (int nj = 0; nj < 4; nj++) {
            int nn = nbase + nj * 8 + c0;
            float b0 = bias[nn], b1 = bias[nn + 1];
            #pragma unroll
            for (int half = 0; half < 2; half++) {
                int mm = mbase + mi * 16 + r0 + half * 8;
                float v0 = acc[mi][nj][half * 2]     + b0;
                float v1 = acc[mi][nj][half * 2 + 1] + b1;
                if (RELU) { v0 = fmaxf(v0, 0.f); v1 = fmaxf(v1, 0.f); }
                size_t off = (size_t)mm * N + nn;
                if (OSPLIT) {
                    __nv_bfloat16 h0, l0, h1, l1;
                    split1(v0, h0, l0); split1(v1, h1, l1);
                    *(__nv_bfloat162*)(Ch + off) = __nv_bfloat162(h0, h1);
                    *(__nv_bfloat162*)(Cl + off) = __nv_bfloat162(l0, l1);
                } else {
                    *(float2*)(C + off) = make_float2(v0, v1);
                }
            }
        }
    }
}

// ---------------- query normalization (QaN) ----------------
__global__ void prep_q_kernel(const float* __restrict__ q) {
    int n = blockIdx.x / H_, h = blockIdx.x % H_;
    int lane = threadIdx.x;
    const float* base = q + n * D_ + h * DH;
    float v0 = base[lane];
    float v1 = base[lane + 32];
    float ss = v0 * v0 + v1 * v1;
    #pragma unroll
    for (int o = 16; o; o >>= 1) ss += __shfl_xor_sync(0xffffffffu, ss, o);
    float f = 1.0f / ((sqrtf(ss) + 1e-6f) * 8.0f * sqrtf(512.0f));
    g_qn[n * D_ + h * DH + lane]      = v0 * f;
    g_qn[n * D_ + h * DH + lane + 32] = v1 * f;
}

// ---------------- QaN scores ----------------
__global__ __launch_bounds__(256) void qa_score_kernel(const float* __restrict__ tgt) {
    __shared__ float qs[NQ_ * D_];
    int tid = threadIdx.x, lane = tid & 31, wid = tid >> 5;
    for (int i = tid; i < NQ_ * D_; i += 256) qs[i] = g_qn[i];
    __syncthreads();

    int r = blockIdx.x * 8 + wid;
    const float* row = tgt + (size_t)r * D_;
    float x[16];
    #pragma unroll
    for (int i = 0; i < 4; i++) {
        float4 v = *(const float4*)(row + i * 128 + lane * 4);
        x[i * 4] = v.x; x[i * 4 + 1] = v.y; x[i * 4 + 2] = v.z; x[i * 4 + 3] = v.w;
    }
    #pragma unroll
    for (int n = 0; n < NQ_; n++) {
        const float* qr = qs + n * D_;
        float s = 0.f;
        #pragma unroll
        for (int i = 0; i < 4; i++) {
            s += x[i * 4]     * qr[i * 128 + lane * 4];
            s += x[i * 4 + 1] * qr[i * 128 + lane * 4 + 1];
            s += x[i * 4 + 2] * qr[i * 128 + lane * 4 + 2];
            s += x[i * 4 + 3] * qr[i * 128 + lane * 4 + 3];
        }
        #pragma unroll
        for (int o = 16; o; o >>= 1) s += __shfl_xor_sync(0xffffffffu, s, o);
        if (lane == 0) g_sc[r * NQ_ + n] = s;
    }
}

// ---------------- QaN output ----------------
__global__ __launch_bounds__(256) void qa_out_kernel(const float* __restrict__ tgt,
                                                     const float* __restrict__ wk) {
    __shared__ float ssc[NQ_ * 48];
    __shared__ float swj[48];
    int bx = blockIdx.x;
    int b = bx >> 7, m = bx & 127;
    int tid = threadIdx.x, lane = tid & 31, wid = tid >> 5;
    int t0 = (m - 1) * W_;

    for (int idx = tid; idx < NQ_ * 48; idx += 256) {
        int n = idx / 48, j = idx % 48;
        int win = m - 1 + (j >> 4);
        float v = NEGV;
        if (win >= 0 && win < NW) v = g_sc[(size_t)(t0 + j) * B_ * NQ_ + b * NQ_ + n];
        ssc[n * 48 + j] = v;
    }
    __syncthreads();

    for (int n = wid; n < NQ_; n += 8) {
        float v0 = ssc[n * 48 + lane];
        float v1 = (lane < 16) ? ssc[n * 48 + 32 + lane] : NEGV;
        float mx = fmaxf(v0, v1);
        #pragma unroll
        for (int o = 16; o; o >>= 1) mx = fmaxf(mx, __shfl_xor_sync(0xffffffffu, mx, o));
        float e0 = __expf(v0 - mx);
        float e1 = (lane < 16) ? __expf(v1 - mx) : 0.f;
        float su = e0 + e1;
        #pragma unroll
        for (int o = 16; o; o >>= 1) su += __shfl_xor_sync(0xffffffffu, su, o);
        float inv = 1.0f / su;
        ssc[n * 48 + lane] = e0 * inv;
        if (lane < 16) ssc[n * 48 + 32 + lane] = e1 * inv;
    }
    __syncthreads();

    if (tid < 48) {
        float acc = 0.f;
        #pragma unroll
        for (int n = 0; n < NQ_; n++) acc += wk[n] * ssc[n * 48 + tid];
        swj[tid] = acc;
    }
    __syncthreads();

    int js = (m == 0) ? 16 : 0;
    int je = (m == NW - 1) ? 32 : 48;
    float acc0 = 0.f, acc1 = 0.f;
    const float* base = tgt + ((size_t)(t0 + js) * B_ + b) * D_ + tid;
    for (int j = js; j < je; j++) {
        float w = swj[j];
        acc0 += w * base[0];
        acc1 += w * base[256];
        base += (size_t)B_ * D_;
    }
    size_t o = ((size_t)b * NW + m) * D_ + tid;
    g_qa[o]       = acc0;
    g_qa[o + 256] = acc1;
}

// ---------------- residual add + LayerNorm ----------------
__device__ __forceinline__ float block_sum(float v, float* red) {
    int lane = threadIdx.x & 31, w = threadIdx.x >> 5;
    __syncthreads();
    #pragma unroll
    for (int o = 16; o; o >>= 1) v += __shfl_xor_sync(0xffffffffu, v, o);
    if (lane == 0) red[w] = v;
    __syncthreads();
    v = (lane < 8) ? red[lane] : 0.f;
    #pragma unroll
    for (int o = 4; o; o >>= 1) v += __shfl_xor_sync(0xffffffffu, v, o);
    return __shfl_sync(0xffffffffu, v, 0);
}

__global__ __launch_bounds__(256) void add_ln_kernel(const float* __restrict__ a,
                                                     const float* __restrict__ bsrc,
                                                     const float* __restrict__ g,
                                                     const float* __restrict__ be,
                                                     float* __restrict__ out,
                                                     __nv_bfloat16* __restrict__ oh,
                                                     __nv_bfloat16* __restrict__ ol,
                                                     int mode) {
    __shared__ float red[8];
    int r = blockIdx.x, tid = threadIdx.x;
    const float* ar = a + (size_t)r * D_;
    const float* br;
    if (mode == 1) {
        int t = r / B_, b = r % B_;
        br = bsrc + (size_t)(b * NW + (t >> 4)) * D_;
    } else {
        br = bsrc + (size_t)r * D_;
    }
    float x0 = ar[tid]       + br[tid];
    float x1 = ar[tid + 256] + br[tid + 256];
    float mu = block_sum(x0 + x1, red) * (1.0f / 512.0f);
    float d0 = x0 - mu, d1 = x1 - mu;
    float var = block_sum(d0 * d0 + d1 * d1, red) * (1.0f / 512.0f);
    float inv = rsqrtf(var + EPS);
    float y0 = d0 * inv * g[tid]       + be[tid];
    float y1 = d1 * inv * g[tid + 256] + be[tid + 256];
    size_t o0 = (size_t)r * D_ + tid, o1 = o0 + 256;
    out[o0] = y0;
    out[o1] = y1;
    if (oh) {
        __nv_bfloat16 h, l;
        split1(y0, h, l); oh[o0] = h; ol[o0] = l;
        split1(y1, h, l); oh[o1] = h; ol[o1] = l;
    }
}

// ---------------- flash attention: 64-row KV chunks, 6 CTAs/SM ----------------
#define A3_KH 0
#define A3_KL 9216
#define A3_VH 18432
#define A3_VL 27648
#define A3_SMEM 36864

__global__ __launch_bounds__(128, 6) void attn3_kernel(
    const __nv_bfloat16* __restrict__ Qh, const __nv_bfloat16* __restrict__ Ql,
    const __nv_bfloat16* __restrict__ KVh, const __nv_bfloat16* __restrict__ KVl,
    __nv_bfloat16* __restrict__ Oh, __nv_bfloat16* __restrict__ Ol)
{
    extern __shared__ char smc[];
    uint32_t uB = smem_u32(smc);
    uint32_t uKh = uB + A3_KH, uKl = uB + A3_KL;
    uint32_t uVh = uB + A3_VH, uVl = uB + A3_VL;

    int qt0 = blockIdx.x * 64, h = blockIdx.y, b = blockIdx.z;
    int tid = threadIdx.x, lane = tid & 31, wid = tid >> 5;

    // stage Q (scaled 1/8) through the K area (64 rows), grab frags, release
    {
        __nv_bfloat162 sc = __floats2bfloat162_rn(0.125f, 0.125f);
        for (int idx = tid; idx < 64 * 32; idx += 128) {
            int i = idx >> 5, dp = idx & 31;
            size_t go = (((size_t)(qt0 + i) * B_ + b) * D_ + h * DH) / 2 + dp;
            __nv_bfloat162 vh = ((const __nv_bfloat162*)Qh)[go];
            __nv_bfloat162 vl = ((const __nv_bfloat162*)Ql)[go];
            ((__nv_bfloat162*)(smc + A3_KH))[i * 36 + dp] = __hmul2(vh, sc);
            ((__nv_bfloat162*)(smc + A3_KL))[i * 36 + dp] = __hmul2(vl, sc);
        }
    }
    __syncthreads();

    uint32_t a_lo = ((lane & 15) * 72 + (lane >> 4) * 8) * 2;
    uint32_t aq[4][4], aql[4][4];
    #pragma unroll
    for (int ks = 0; ks < 4; ks++) {
        ldsm4(aq[ks],  uKh + (wid * 16) * 144 + a_lo + ks * 32);
        ldsm4(aql[ks], uKl + (wid * 16) * 144 + a_lo + ks * 32);
    }
    __syncthreads();

    // K/V chunk loader: 64 s-rows
    auto loadKV = [&](int sch) {
        for (int idx = tid; idx < 512; idx += 128) {
            int s = idx >> 3, dg = (idx & 7) * 8;
            size_t gk = ((size_t)(sch + s) * B_ + b) * 1024 + h * DH + dg;
            size_t gv = gk + 512;
            uint32_t so = (s * 72 + dg) * 2;
            *(uint4*)(smc + A3_KH + so) = *(const uint4*)(KVh + gk);
            *(uint4*)(smc + A3_KL + so) = *(const uint4*)(KVl + gk);
            *(uint4*)(smc + A3_VH + so) = *(const uint4*)(KVh + gv);
            *(uint4*)(smc + A3_VL + so) = *(const uint4*)(KVl + gv);
        }
    };
    loadKV(0);

    uint32_t b_lo = ((((lane >> 4) & 1) * 8 + (lane & 7)) * 72 + ((lane >> 3) & 1) * 8) * 2;
    uint32_t v_lo = ((lane & 15) * 72 + (lane >> 4) * 8) * 2;

    float oacc[8][4];
    #pragma unroll
    for (int t = 0; t < 8; t++)
        #pragma unroll
        for (int k = 0; k < 4; k++) oacc[t][k] = 0.f;
    float mrA = -1e30f, mrB = -1e30f, lrA = 0.f, lrB = 0.f;

    for (int c = 0; c < 8; c++) {
        __syncthreads();   // KV chunk ready

        // QK scores: 8 n8-tiles over s=64
        float cf[8][4];
        #pragma unroll
        for (int st = 0; st < 4; st++) {
            float* c0 = cf[2 * st];
            float* c1 = cf[2 * st + 1];
            #pragma unroll
            for (int k = 0; k < 4; k++) { c0[k] = 0.f; c1[k] = 0.f; }
            uint32_t kb  = uKh + (st * 16) * 144 + b_lo;
            uint32_t klb = uKl + (st * 16) * 144 + b_lo;
            #pragma unroll
            for (int ks = 0; ks < 4; ks++) {
                uint32_t kh[4], kl[4];
                ldsm4(kh, kb + ks * 32);
                ldsm4(kl, klb + ks * 32);
                mma_bf16(c0, aq[ks], kh[0], kh[1]);
                mma_bf16(c1, aq[ks], kh[2], kh[3]);
                mma_bf16(c0, aq[ks], kl[0], kl[1]);
                mma_bf16(c1, aq[ks], kl[2], kl[3]);
                mma_bf16(c0, aql[ks], kh[0], kh[1]);
                mma_bf16(c1, aql[ks], kh[2], kh[3]);
            }
        }

        // online softmax
        float mA = cf[0][0], mB = cf[0][2];
        #pragma unroll
        for (int t = 0; t < 8; t++) {
            mA = fmaxf(mA, fmaxf(cf[t][0], cf[t][1]));
            mB = fmaxf(mB, fmaxf(cf[t][2], cf[t][3]));
        }
        mA = fmaxf(mA, __shfl_xor_sync(0xffffffffu, mA, 1));
        mA = fmaxf(mA, __shfl_xor_sync(0xffffffffu, mA, 2));
        mB = fmaxf(mB, __shfl_xor_sync(0xffffffffu, mB, 1));
        mB = fmaxf(mB, __shfl_xor_sync(0xffffffffu, mB, 2));
        float mnA = fmaxf(mrA, mA), mnB = fmaxf(mrB, mB);
        float alA = __expf(mrA - mnA), alB = __expf(mrB - mnB);
        mrA = mnA; mrB = mnB;
        lrA *= alA; lrB *= alB;
        #pragma unroll
        for (int t = 0; t < 8; t++) {
            oacc[t][0] *= alA; oacc[t][1] *= alA;
            oacc[t][2] *= alB; oacc[t][3] *= alB;
        }
        float sA = 0.f, sB = 0.f;
        #pragma unroll
        for (int t = 0; t < 8; t++) {
            cf[t][0] = __expf(cf[t][0] - mnA);
            cf[t][1] = __expf(cf[t][1] - mnA);
            cf[t][2] = __expf(cf[t][2] - mnB);
            cf[t][3] = __expf(cf[t][3] - mnB);
            sA += cf[t][0] + cf[t][1];
            sB += cf[t][2] + cf[t][3];
        }
        sA += __shfl_xor_sync(0xffffffffu, sA, 1);
        sA += __shfl_xor_sync(0xffffffffu, sA, 2);
        sB += __shfl_xor_sync(0xffffffffu, sB, 1);
        sB += __shfl_xor_sync(0xffffffffu, sB, 2);
        lrA += sA; lrB += sB;

        // pack P into A-frags (hi/lo split in registers)
        uint32_t pah[4][4], pal[4][4];
        #pragma unroll
        for (int j = 0; j < 4; j++) {
            #pragma unroll
            for (int q = 0; q < 2; q++) {
                float* cc = cf[2 * j + q];
                __nv_bfloat16 h0, l0, h1, l1;
                split1(cc[0], h0, l0); split1(cc[1], h1, l1);
                __nv_bfloat162 vh(h0, h1), vl(l0, l1);
                pah[j][2 * q]     = *reinterpret_cast<uint32_t*>(&vh);
                pal[j][2 * q]     = *reinterpret_cast<uint32_t*>(&vl);
                split1(cc[2], h0, l0); split1(cc[3], h1, l1);
                __nv_bfloat162 wh2(h0, h1), wl2(l0, l1);
                pah[j][2 * q + 1] = *reinterpret_cast<uint32_t*>(&wh2);
                pal[j][2 * q + 1] = *reinterpret_cast<uint32_t*>(&wl2);
            }
        }

        // PV accumulate
        #pragma unroll
        for (int j = 0; j < 4; j++) {
            uint32_t vbase  = uVh + v_lo + j * 16 * 144;
            uint32_t vlbase = uVl + v_lo + j * 16 * 144;
            #pragma unroll
            for (int dd = 0; dd < 4; dd++) {
                uint32_t vh[4], vl[4];
                ldsm4t(vh, vbase + dd * 32);
                ldsm4t(vl, vlbase + dd * 32);
                mma_bf16(oacc[2 * dd],     pah[j], vh[0], vh[1]);
                mma_bf16(oacc[2 * dd + 1], pah[j], vh[2], vh[3]);
                mma_bf16(oacc[2 * dd],     pah[j], vl[0], vl[1]);
                mma_bf16(oacc[2 * dd + 1], pah[j], vl[2], vl[3]);
                mma_bf16(oacc[2 * dd],     pal[j], vh[0], vh[1]);
                mma_bf16(oacc[2 * dd + 1], pal[j], vh[2], vh[3]);
            }
        }

        __syncthreads();   // V reads done before overwrite
        if (c < 7) loadKV((c + 1) * 64);
    }

    float invA = 1.0f / lrA, invB = 1.0f / lrB;
    int r0 = lane >> 2, c0 = (lane & 3) * 2;
    int qA = qt0 + wid * 16 + r0;
    #pragma unroll
    for (int t = 0; t < 8; t++) {
        int d = h * DH + t * 8 + c0;
        size_t offA = ((size_t)qA * B_ + b) * D_ + d;
        size_t offB = ((size_t)(qA + 8) * B_ + b) * D_ + d;
        __nv_bfloat16 h0, l0, h1, l1;
        split1(oacc[t][0] * invA, h0, l0); split1(oacc[t][1] * invA, h1, l1);
        *(__nv_bfloat162*)(Oh + offA) = __nv_bfloat162(h0, h1);
        *(__nv_bfloat162*)(Ol + offA) = __nv_bfloat162(l0, l1);
        split1(oacc[t][2] * invB, h0, l0); split1(oacc[t][3] * invB, h1, l1);
        *(__nv_bfloat162*)(Oh + offB) = __nv_bfloat162(h0, h1);
        *(__nv_bfloat162*)(Ol + offB) = __nv_bfloat162(l0, l1);
    }
}

// ---------------- host launcher ----------------
extern "C" void kernel_launch(void* const* d_in, const int* in_sizes, int n_in,
                              void* d_out, int out_size) {
    const float* tgt     = (const float*)d_in[0];
    const float* memory  = (const float*)d_in[1];
    const float* queries = (const float*)d_in[2];
    const float* wk      = (const float*)d_in[3];
    const float* in_w    = (const float*)d_in[4];
    const float* in_b    = (const float*)d_in[5];
    const float* out_w   = (const float*)d_in[6];
    const float* out_b   = (const float*)d_in[7];
    const float* l1w     = (const float*)d_in[8];
    const float* l1b     = (const float*)d_in[9];
    const float* l2w     = (const float*)d_in[10];
    const float* l2b     = (const float*)d_in[11];
    const float* ln1g    = (const float*)d_in[12];
    const float* ln1b    = (const float*)d_in[13];
    const float* ln2g    = (const float*)d_in[14];
    const float* ln2b    = (const float*)d_in[15];
    const float* ln3g    = (const float*)d_in[16];
    const float* ln3b    = (const float*)d_in[17];
    float* out = (float*)d_out;

    float *qa, *x1, *qb, *kv, *tmp, *x2;
    __nv_bfloat16 *x1h, *x1l, *x2h, *x2l, *obh, *obl, *hh, *hl, *memh, *meml, *wh, *wl;
    cudaGetSymbolAddress((void**)&qa,  g_qa);
    cudaGetSymbolAddress((void**)&x1,  g_x1);
    cudaGetSymbolAddress((void**)&qb,  g_q);
    cudaGetSymbolAddress((void**)&kv,  g_kv);
    cudaGetSymbolAddress((void**)&tmp, g_tmp);
    cudaGetSymbolAddress((void**)&x2,  g_x2);
    cudaGetSymbolAddress((void**)&x1h, g_x1h); cudaGetSymbolAddress((void**)&x1l, g_x1l);
    cudaGetSymbolAddress((void**)&x2h, g_x2h); cudaGetSymbolAddress((void**)&x2l, g_x2l);
    cudaGetSymbolAddress((void**)&obh, g_obh); cudaGetSymbolAddress((void**)&obl, g_obl);
    cudaGetSymbolAddress((void**)&hh,  g_hh);  cudaGetSymbolAddress((void**)&hl,  g_hl);
    cudaGetSymbolAddress((void**)&memh, g_memh); cudaGetSymbolAddress((void**)&meml, g_meml);
    cudaGetSymbolAddress((void**)&wh,  g_wh);  cudaGetSymbolAddress((void**)&wl,  g_wl);

    __nv_bfloat16* qh  = (__nv_bfloat16*)qb;
    __nv_bfloat16* ql  = qh + (size_t)T_ * B_ * D_;
    __nv_bfloat16* kvh = (__nv_bfloat16*)kv;
    __nv_bfloat16* kvl = kvh + (size_t)S_ * B_ * 2 * D_;

    cudaFuncSetAttribute(attn3_kernel, cudaFuncAttributeMaxDynamicSharedMemorySize, A3_SMEM);
    cudaFuncSetAttribute(gemm_bf16_v2<0,0>, cudaFuncAttributeMaxDynamicSharedMemorySize, GT_SMEM);
    cudaFuncSetAttribute(gemm_bf16_v2<0,1>, cudaFuncAttributeMaxDynamicSharedMemorySize, GT_SMEM);
    cudaFuncSetAttribute(gemm_bf16_v2<1,1>, cudaFuncAttributeMaxDynamicSharedMemorySize, GT_SMEM);

    const int MR = T_ * B_;

    // ---- fork: side stream runs split_all -> KV-proj; main runs QaN chain then
    //      Q-proj concurrently with KV-proj ----
    cudaStream_t s2;
    cudaEvent_t evFork, evSplit, evKV;
    bool forked = (cudaStreamCreateWithFlags(&s2, cudaStreamNonBlocking) == cudaSuccess);
    if (forked) {
        forked = (cudaEventCreateWithFlags(&evFork,  cudaEventDisableTiming) == cudaSuccess) &&
                 (cudaEventCreateWithFlags(&evSplit, cudaEventDisableTiming) == cudaSuccess) &&
                 (cudaEventCreateWithFlags(&evKV,    cudaEventDisableTiming) == cudaSuccess);
    }

    if (forked) {
        cudaEventRecord(evFork, 0);
        cudaStreamWaitEvent(s2, evFork, 0);

        split_all_kernel<<<5120, 256, 0, s2>>>((const float4*)in_w, (const float4*)out_w,
                                               (const float4*)l1w, (const float4*)l2w,
                                               (const float4*)memory, wh, wl, memh, meml);
        cudaEventRecord(evSplit, s2);
        gemm_bf16_v2<0, 1><<<dim3(8, 32), 512, GT_SMEM, s2>>>(memh, meml,
                                                              wh + WOFF_IN + 512 * 512,
                                                              wl + WOFF_IN + 512 * 512, in_b + 512,
                                                              nullptr, kvh, kvl, S_ * B_, 1024, 512);
        cudaEventRecord(evKV, s2);

        prep_q_kernel<<<NQ_ * H_, 32>>>(queries);
        qa_score_kernel<<<MR / 8, 256>>>(tgt);
        qa_out_kernel<<<B_ * NW, 256>>>(tgt, wk);
        add_ln_kernel<<<MR, 256>>>(tgt, qa, ln1g, ln1b, x1, x1h, x1l, 1);

        cudaStreamWaitEvent(0, evSplit, 0);
        gemm_bf16_v2<0, 1><<<dim3(4, 128), 512, GT_SMEM>>>(x1h, x1l, wh + WOFF_IN, wl + WOFF_IN,
                                                           in_b, nullptr, qh, ql, MR, 512, 512);
        cudaStreamWaitEvent(0, evKV, 0);
    } else {
        split_all_kernel<<<5120, 256>>>((const float4*)in_w, (const float4*)out_w,
                                        (const float4*)l1w, (const float4*)l2w,
                                        (const float4*)memory, wh, wl, memh, meml);
        gemm_bf16_v2<0, 1><<<dim3(8, 32), 512, GT_SMEM>>>(memh, meml, wh + WOFF_IN + 512 * 512,
                                                          wl + WOFF_IN + 512 * 512, in_b + 512,
                                                          nullptr, kvh, kvl, S_ * B_, 1024, 512);
        prep_q_kernel<<<NQ_ * H_, 32>>>(queries);
        qa_score_kernel<<<MR / 8, 256>>>(tgt);
        qa_out_kernel<<<B_ * NW, 256>>>(tgt, wk);
        add_ln_kernel<<<MR, 256>>>(tgt, qa, ln1g, ln1b, x1, x1h, x1l, 1);
        gemm_bf16_v2<0, 1><<<dim3(4, 128), 512, GT_SMEM>>>(x1h, x1l, wh + WOFF_IN, wl + WOFF_IN,
                                                           in_b, nullptr, qh, ql, MR, 512, 512);
    }

    // attention (flash, 64-row chunks)
    attn3_kernel<<<dim3(T_ / 64, H_, B_), 128, A3_SMEM>>>(qh, ql, kvh, kvl, obh, obl);
    // out proj + LN2
    gemm_bf16_v2<0, 0><<<dim3(4, 128), 512, GT_SMEM>>>(obh, obl, wh + WOFF_OUT, wl + WOFF_OUT,
                                                       out_b, tmp, nullptr, nullptr, MR, 512, 512);
    add_ln_kernel<<<MR, 256>>>(x1, tmp, ln2g, ln2b, x2, x2h, x2l, 0);
    // FFN + LN3
    gemm_bf16_v2<1, 1><<<dim3(16, 128), 512, GT_SMEM>>>(x2h, x2l, wh + WOFF_L1, wl + WOFF_L1,
                                                        l1b, nullptr, hh, hl, MR, DFF_, 512);
    gemm_bf16_v2<0, 0><<<dim3(4, 128), 512, GT_SMEM>>>(hh, hl, wh + WOFF_L2, wl + WOFF_L2,
                                                       l2b, tmp, nullptr, nullptr, MR, 512, DFF_);
    add_ln_kernel<<<MR, 256>>>(x2, tmp, ln3g, ln3b, out, nullptr, nullptr, 0);
    // s2/events intentionally not destroyed: the captured graph references them and
    // kernel_launch only executes at capture time (bounded, no device allocation).
}

// round 17
// speedup vs baseline: 1.0586x; 1.0586x over previous
#include <cuda_runtime.h>
#include <cuda_bf16.h>
#include <math.h>
#include <stdint.h>

#define T_   2048
#define B_   8
#define S_   512
#define D_   512
#define H_   8
#define DH   64
#define DFF_ 2048
#define NQ_  10
#define W_   16
#define NW   128
#define EPS  1e-5f
#define NEGV -1e30f

// ---------------- scratch ----------------
__device__ float g_qn[NQ_ * D_];
__device__ float g_sc[T_ * B_ * NQ_];
__device__ float g_qa[B_ * NW * D_];
__device__ float g_x1[T_ * B_ * D_];
__device__ float g_q [T_ * B_ * D_];
__device__ float g_kv[S_ * B_ * 2 * D_];
__device__ float g_tmp[T_ * B_ * D_];
__device__ float g_x2[T_ * B_ * D_];

__device__ __nv_bfloat16 g_x1h[T_ * B_ * D_], g_x1l[T_ * B_ * D_];
__device__ __nv_bfloat16 g_x2h[T_ * B_ * D_], g_x2l[T_ * B_ * D_];
__device__ __nv_bfloat16 g_obh[T_ * B_ * D_], g_obl[T_ * B_ * D_];
__device__ __nv_bfloat16 g_hh [T_ * B_ * DFF_], g_hl [T_ * B_ * DFF_];
__device__ __nv_bfloat16 g_memh[S_ * B_ * D_], g_meml[S_ * B_ * D_];
#define WOFF_IN  0
#define WOFF_OUT (1536 * 512)
#define WOFF_L1  (WOFF_OUT + 512 * 512)
#define WOFF_L2  (WOFF_L1 + 2048 * 512)
#define WTOT     (WOFF_L2 + 512 * 2048)
__device__ __nv_bfloat16 g_wh[WTOT], g_wl[WTOT];

// ---------------- helpers ----------------
__device__ __forceinline__ uint32_t smem_u32(const void* p) {
    uint32_t a;
    asm("{ .reg .u64 t; cvta.to.shared.u64 t, %1; cvt.u32.u64 %0, t; }" : "=r"(a) : "l"(p));
    return a;
}
__device__ __forceinline__ void split1(float a, __nv_bfloat16& h, __nv_bfloat16& l) {
    h = __float2bfloat16(a);
    l = __float2bfloat16(a - __bfloat162float(h));
}
__device__ __forceinline__ void ldsm4(uint32_t* r, uint32_t addr) {
    asm volatile("ldmatrix.sync.aligned.m8n8.x4.shared.b16 {%0,%1,%2,%3}, [%4];"
        : "=r"(r[0]), "=r"(r[1]), "=r"(r[2]), "=r"(r[3]) : "r"(addr));
}
__device__ __forceinline__ void ldsm4t(uint32_t* r, uint32_t addr) {
    asm volatile("ldmatrix.sync.aligned.m8n8.x4.trans.shared.b16 {%0,%1,%2,%3}, [%4];"
        : "=r"(r[0]), "=r"(r[1]), "=r"(r[2]), "=r"(r[3]) : "r"(addr));
}
__device__ __forceinline__ void mma_bf16(float* d, const uint32_t* a, uint32_t b0, uint32_t b1) {
    asm("mma.sync.aligned.m16n8k16.row.col.f32.bf16.bf16.f32 "
        "{%0,%1,%2,%3}, {%4,%5,%6,%7}, {%8,%9}, {%0,%1,%2,%3};"
        : "+f"(d[0]), "+f"(d[1]), "+f"(d[2]), "+f"(d[3])
        : "r"(a[0]), "r"(a[1]), "r"(a[2]), "r"(a[3]), "r"(b0), "r"(b1));
}
__device__ __forceinline__ void cpa16(uint32_t d, const void* s) {
    asm volatile("cp.async.cg.shared.global [%0], [%1], 16;" :: "r"(d), "l"(s));
}
#define CP_COMMIT() asm volatile("cp.async.commit_group;")
#define CP_WAIT1()  asm volatile("cp.async.wait_group 1;")

#define MMA12(ACC, AH, AL, B0H, B1H, B0L, B1L) do {      \
    mma_bf16(ACC[0], AH, B0H[0], B0H[1]);                \
    mma_bf16(ACC[1], AH, B0H[2], B0H[3]);                \
    mma_bf16(ACC[2], AH, B1H[0], B1H[1]);                \
    mma_bf16(ACC[3], AH, B1H[2], B1H[3]);                \
    mma_bf16(ACC[0], AH, B0L[0], B0L[1]);                \
    mma_bf16(ACC[1], AH, B0L[2], B0L[3]);                \
    mma_bf16(ACC[2], AH, B1L[0], B1L[1]);                \
    mma_bf16(ACC[3], AH, B1L[2], B1L[3]);                \
    mma_bf16(ACC[0], AL, B0H[0], B0H[1]);                \
    mma_bf16(ACC[1], AL, B0H[2], B0H[3]);                \
    mma_bf16(ACC[2], AL, B1H[0], B1H[1]);                \
    mma_bf16(ACC[3], AL, B1H[2], B1H[3]);                \
} while (0)

// ---------------- fused fp32 -> bf16 hi/lo split ----------------
__device__ __forceinline__ void split4_store(float4 v, __nv_bfloat162* dh, __nv_bfloat162* dl, int j) {
    __nv_bfloat16 hx, lx, hy, ly, hz, lz, hw, lw;
    split1(v.x, hx, lx); split1(v.y, hy, ly);
    split1(v.z, hz, lz); split1(v.w, hw, lw);
    dh[2 * j]     = __nv_bfloat162(hx, hy);
    dh[2 * j + 1] = __nv_bfloat162(hz, hw);
    dl[2 * j]     = __nv_bfloat162(lx, ly);
    dl[2 * j + 1] = __nv_bfloat162(lz, lw);
}

__global__ void split_all_kernel(const float4* __restrict__ inw, const float4* __restrict__ outw,
                                 const float4* __restrict__ l1w, const float4* __restrict__ l2w,
                                 const float4* __restrict__ mem,
                                 __nv_bfloat16* __restrict__ wh, __nv_bfloat16* __restrict__ wl,
                                 __nv_bfloat16* __restrict__ memh, __nv_bfloat16* __restrict__ meml) {
    int i = blockIdx.x * 256 + threadIdx.x;
    const int n0 = 1536 * 512 / 4;
    const int n1 = n0 + 512 * 512 / 4;
    const int n2 = n1 + 2048 * 512 / 4;
    const int n3 = n2 + 512 * 2048 / 4;
    const int n4 = n3 + S_ * B_ * D_ / 4;
    if (i >= n4) return;
    const float4* src; __nv_bfloat162 *dh, *dl; int j;
    if (i < n0)      { j = i;      src = inw;  dh = (__nv_bfloat162*)(wh + WOFF_IN);  dl = (__nv_bfloat162*)(wl + WOFF_IN); }
    else if (i < n1) { j = i - n0; src = outw; dh = (__nv_bfloat162*)(wh + WOFF_OUT); dl = (__nv_bfloat162*)(wl + WOFF_OUT); }
    else if (i < n2) { j = i - n1; src = l1w;  dh = (__nv_bfloat162*)(wh + WOFF_L1);  dl = (__nv_bfloat162*)(wl + WOFF_L1); }
    else if (i < n3) { j = i - n2; src = l2w;  dh = (__nv_bfloat162*)(wh + WOFF_L2);  dl = (__nv_bfloat162*)(wl + WOFF_L2); }
    else             { j = i - n3; src = mem;  dh = (__nv_bfloat162*)memh;            dl = (__nv_bfloat162*)meml; }
    split4_store(src[j], dh, dl, j);
}

// ================= HMMA GEMM: 512 thr / 16 warps, warp tile 32x32 =================
#define STG_ELEM (128 * 40)
#define STG_BYTE (STG_ELEM * 2)
#define GT_SMEM  (8 * STG_BYTE)

template<int RELU, int OSPLIT>
__global__ __launch_bounds__(512, 2) void gemm_bf16_v2(
    const __nv_bfloat16* __restrict__ Ah, const __nv_bfloat16* __restrict__ Al,
    const __nv_bfloat16* __restrict__ Bh, const __nv_bfloat16* __restrict__ Bl,
    const float* __restrict__ bias, float* __restrict__ C,
    __nv_bfloat16* __restrict__ Ch, __nv_bfloat16* __restrict__ Cl,
    int M, int N, int K)
{
    extern __shared__ __nv_bfloat16 dsm[];
    __nv_bfloat16* sAh = dsm;
    __nv_bfloat16* sAl = dsm + 2 * STG_ELEM;
    __nv_bfloat16* sBh = dsm + 4 * STG_ELEM;
    __nv_bfloat16* sBl = dsm + 6 * STG_ELEM;

    int tid = threadIdx.x, lane = tid & 31, wid = tid >> 5;
    int m0 = blockIdx.y * 128, n0 = blockIdx.x * 128;
    int warp_m = wid >> 2, warp_n = wid & 3;

    float acc[2][4][4];
    #pragma unroll
    for (int i = 0; i < 2; i++)
        #pragma unroll
        for (int j = 0; j < 4; j++)
            #pragma unroll
            for (int k = 0; k < 4; k++) acc[i][j][k] = 0.f;

    uint32_t uAh = smem_u32(sAh), uAl = smem_u32(sAl);
    uint32_t uBh = smem_u32(sBh), uBl = smem_u32(sBl);

    uint32_t a_off = ((warp_m * 32 + (lane & 15)) * 40 + (lane >> 4) * 8) * 2;
    uint32_t b_off = ((warp_n * 32 + ((lane >> 4) & 1) * 8 + (lane & 7)) * 40
                      + ((lane >> 3) & 1) * 8) * 2;

    int lrow = tid >> 2;
    int lp   = (tid & 3) * 8;
    uint32_t sdst = (lrow * 40 + lp) * 2;
    const __nv_bfloat16* Arow  = Ah + (size_t)(m0 + lrow) * K + lp;
    const __nv_bfloat16* Alrow = Al + (size_t)(m0 + lrow) * K + lp;
    const __nv_bfloat16* Brow  = Bh + (size_t)(n0 + lrow) * K + lp;
    const __nv_bfloat16* Blrow = Bl + (size_t)(n0 + lrow) * K + lp;

    auto prefetch = [&](int kc, int st) {
        uint32_t so = st * STG_BYTE + sdst;
        cpa16(uAh + so, Arow + kc);
        cpa16(uAl + so, Alrow + kc);
        cpa16(uBh + so, Brow + kc);
        cpa16(uBl + so, Blrow + kc);
        CP_COMMIT();
    };

    int nch = K >> 5;
    prefetch(0, 0);
    prefetch(32, 1);

    for (int c = 0; c < nch; c++) {
        CP_WAIT1();
        __syncthreads();
        uint32_t stb = (c & 1) * STG_BYTE;
        #pragma unroll
        for (int ks = 0; ks < 2; ks++) {
            uint32_t b0h[4], b1h[4], b0l[4], b1l[4];
            ldsm4(b0h, uBh + stb + b_off + ks * 32);
            ldsm4(b1h, uBh + stb + b_off + 1280 + ks * 32);
            ldsm4(b0l, uBl + stb + b_off + ks * 32);
            ldsm4(b1l, uBl + stb + b_off + 1280 + ks * 32);
            #pragma unroll
            for (int mi = 0; mi < 2; mi++) {
                uint32_t ah[4], al[4];
                ldsm4(ah, uAh + stb + a_off + mi * 1280 + ks * 32);
                ldsm4(al, uAl + stb + a_off + mi * 1280 + ks * 32);
                MMA12(acc[mi], ah, al, b0h, b1h, b0l, b1l);
            }
        }
        __syncthreads();
        int nk = c + 2;
        if (nk < nch) prefetch(nk << 5, nk & 1);
    }

    int r0 = lane >> 2, c0 = (lane & 3) * 2;
    int mbase = m0 + warp_m * 32, nbase = n0 + warp_n * 32;
    #pragma unroll
    for (int mi = 0; mi < 2; mi++) {
        #pragma unroll
        for (int nj = 0; nj < 4; nj++) {
            int nn = nbase + nj * 8 + c0;
            float b0 = bias[nn], b1 = bias[nn + 1];
            #pragma unroll
            for (int half = 0; half < 2; half++) {
                int mm = mbase + mi * 16 + r0 + half * 8;
                float v0 = acc[mi][nj][half * 2]     + b0;
                float v1 = acc[mi][nj][half * 2 + 1] + b1;
                if (RELU) { v0 = fmaxf(v0, 0.f); v1 = fmaxf(v1, 0.f); }
                size_t off = (size_t)mm * N + nn;
                if (OSPLIT) {
                    __nv_bfloat16 h0, l0, h1, l1;
                    split1(v0, h0, l0); split1(v1, h1, l1);
                    *(__nv_bfloat162*)(Ch + off) = __nv_bfloat162(h0, h1);
                    *(__nv_bfloat162*)(Cl + off) = __nv_bfloat162(l0, l1);
                } else {
                    *(float2*)(C + off) = make_float2(v0, v1);
                }
            }
        }
    }
}

// ---------------- query normalization (QaN) ----------------
__global__ void prep_q_kernel(const float* __restrict__ q) {
    int n = blockIdx.x / H_, h = blockIdx.x % H_;
    int lane = threadIdx.x;
    const float* base = q + n * D_ + h * DH;
    float v0 = base[lane];
    float v1 = base[lane + 32];
    float ss = v0 * v0 + v1 * v1;
    #pragma unroll
    for (int o = 16; o; o >>= 1) ss += __shfl_xor_sync(0xffffffffu, ss, o);
    float f = 1.0f / ((sqrtf(ss) + 1e-6f) * 8.0f * sqrtf(512.0f));
    g_qn[n * D_ + h * DH + lane]      = v0 * f;
    g_qn[n * D_ + h * DH + lane + 32] = v1 * f;
}

// ---------------- QaN scores ----------------
__global__ __launch_bounds__(256) void qa_score_kernel(const float* __restrict__ tgt) {
    __shared__ float qs[NQ_ * D_];
    int tid = threadIdx.x, lane = tid & 31, wid = tid >> 5;
    for (int i = tid; i < NQ_ * D_; i += 256) qs[i] = g_qn[i];
    __syncthreads();

    int r = blockIdx.x * 8 + wid;
    const float* row = tgt + (size_t)r * D_;
    float x[16];
    #pragma unroll
    for (int i = 0; i < 4; i++) {
        float4 v = *(const float4*)(row + i * 128 + lane * 4);
        x[i * 4] = v.x; x[i * 4 + 1] = v.y; x[i * 4 + 2] = v.z; x[i * 4 + 3] = v.w;
    }
    #pragma unroll
    for (int n = 0; n < NQ_; n++) {
        const float* qr = qs + n * D_;
        float s = 0.f;
        #pragma unroll
        for (int i = 0; i < 4; i++) {
            s += x[i * 4]     * qr[i * 128 + lane * 4];
            s += x[i * 4 + 1] * qr[i * 128 + lane * 4 + 1];
            s += x[i * 4 + 2] * qr[i * 128 + lane * 4 + 2];
            s += x[i * 4 + 3] * qr[i * 128 + lane * 4 + 3];
        }
        #pragma unroll
        for (int o = 16; o; o >>= 1) s += __shfl_xor_sync(0xffffffffu, s, o);
        if (lane == 0) g_sc[r * NQ_ + n] = s;
    }
}

// ---------------- QaN output ----------------
__global__ __launch_bounds__(256) void qa_out_kernel(const float* __restrict__ tgt,
                                                     const float* __restrict__ wk) {
    __shared__ float ssc[NQ_ * 48];
    __shared__ float swj[48];
    int bx = blockIdx.x;
    int b = bx >> 7, m = bx & 127;
    int tid = threadIdx.x, lane = tid & 31, wid = tid >> 5;
    int t0 = (m - 1) * W_;

    for (int idx = tid; idx < NQ_ * 48; idx += 256) {
        int n = idx / 48, j = idx % 48;
        int win = m - 1 + (j >> 4);
        float v = NEGV;
        if (win >= 0 && win < NW) v = g_sc[(size_t)(t0 + j) * B_ * NQ_ + b * NQ_ + n];
        ssc[n * 48 + j] = v;
    }
    __syncthreads();

    for (int n = wid; n < NQ_; n += 8) {
        float v0 = ssc[n * 48 + lane];
        float v1 = (lane < 16) ? ssc[n * 48 + 32 + lane] : NEGV;
        float mx = fmaxf(v0, v1);
        #pragma unroll
        for (int o = 16; o; o >>= 1) mx = fmaxf(mx, __shfl_xor_sync(0xffffffffu, mx, o));
        float e0 = __expf(v0 - mx);
        float e1 = (lane < 16) ? __expf(v1 - mx) : 0.f;
        float su = e0 + e1;
        #pragma unroll
        for (int o = 16; o; o >>= 1) su += __shfl_xor_sync(0xffffffffu, su, o);
        float inv = 1.0f / su;
        ssc[n * 48 + lane] = e0 * inv;
        if (lane < 16) ssc[n * 48 + 32 + lane] = e1 * inv;
    }
    __syncthreads();

    if (tid < 48) {
        float acc = 0.f;
        #pragma unroll
        for (int n = 0; n < NQ_; n++) acc += wk[n] * ssc[n * 48 + tid];
        swj[tid] = acc;
    }
    __syncthreads();

    int js = (m == 0) ? 16 : 0;
    int je = (m == NW - 1) ? 32 : 48;
    float acc0 = 0.f, acc1 = 0.f;
    const float* base = tgt + ((size_t)(t0 + js) * B_ + b) * D_ + tid;
    for (int j = js; j < je; j++) {
        float w = swj[j];
        acc0 += w * base[0];
        acc1 += w * base[256];
        base += (size_t)B_ * D_;
    }
    size_t o = ((size_t)b * NW + m) * D_ + tid;
    g_qa[o]       = acc0;
    g_qa[o + 256] = acc1;
}

// ---------------- residual add + LayerNorm ----------------
__device__ __forceinline__ float block_sum(float v, float* red) {
    int lane = threadIdx.x & 31, w = threadIdx.x >> 5;
    __syncthreads();
    #pragma unroll
    for (int o = 16; o; o >>= 1) v += __shfl_xor_sync(0xffffffffu, v, o);
    if (lane == 0) red[w] = v;
    __syncthreads();
    v = (lane < 8) ? red[lane] : 0.f;
    #pragma unroll
    for (int o = 4; o; o >>= 1) v += __shfl_xor_sync(0xffffffffu, v, o);
    return __shfl_sync(0xffffffffu, v, 0);
}

__global__ __launch_bounds__(256) void add_ln_kernel(const float* __restrict__ a,
                                                     const float* __restrict__ bsrc,
                                                     const float* __restrict__ g,
                                                     const float* __restrict__ be,
                                                     float* __restrict__ out,
                                                     __nv_bfloat16* __restrict__ oh,
                                                     __nv_bfloat16* __restrict__ ol,
                                                     int mode) {
    __shared__ float red[8];
    int r = blockIdx.x, tid = threadIdx.x;
    const float* ar = a + (size_t)r * D_;
    const float* br;
    if (mode == 1) {
        int t = r / B_, b = r % B_;
        br = bsrc + (size_t)(b * NW + (t >> 4)) * D_;
    } else {
        br = bsrc + (size_t)r * D_;
    }
    float x0 = ar[tid]       + br[tid];
    float x1 = ar[tid + 256] + br[tid + 256];
    float mu = block_sum(x0 + x1, red) * (1.0f / 512.0f);
    float d0 = x0 - mu, d1 = x1 - mu;
    float var = block_sum(d0 * d0 + d1 * d1, red) * (1.0f / 512.0f);
    float inv = rsqrtf(var + EPS);
    float y0 = d0 * inv * g[tid]       + be[tid];
    float y1 = d1 * inv * g[tid + 256] + be[tid + 256];
    size_t o0 = (size_t)r * D_ + tid, o1 = o0 + 256;
    out[o0] = y0;
    out[o1] = y1;
    if (oh) {
        __nv_bfloat16 h, l;
        split1(y0, h, l); oh[o0] = h; ol[o0] = l;
        split1(y1, h, l); oh[o1] = h; ol[o1] = l;
    }
}

// ---------------- flash attention v4: 128 q-rows/CTA, halved KV traffic ----------------
// 256 threads / 8 warps; each warp owns 16 q rows. KV chunk = 128 s-rows in smem,
// processed as two 64-row sub-chunks (register relief); online softmax per sub-chunk.
#define A3_KH 0
#define A3_KL 18432
#define A3_VH 36864
#define A3_VL 55296
#define A3_SMEM 73728

__global__ __launch_bounds__(256, 2) void attn4_kernel(
    const __nv_bfloat16* __restrict__ Qh, const __nv_bfloat16* __restrict__ Ql,
    const __nv_bfloat16* __restrict__ KVh, const __nv_bfloat16* __restrict__ KVl,
    __nv_bfloat16* __restrict__ Oh, __nv_bfloat16* __restrict__ Ol)
{
    extern __shared__ char smc[];
    uint32_t uB = smem_u32(smc);
    uint32_t uKh = uB + A3_KH, uKl = uB + A3_KL;
    uint32_t uVh = uB + A3_VH, uVl = uB + A3_VL;

    int qt0 = blockIdx.x * 128, h = blockIdx.y, b = blockIdx.z;
    int tid = threadIdx.x, lane = tid & 31, wid = tid >> 5;

    // stage Q (scaled 1/8): 128 rows through the K area, grab frags, release
    {
        __nv_bfloat162 sc = __floats2bfloat162_rn(0.125f, 0.125f);
        for (int idx = tid; idx < 128 * 32; idx += 256) {
            int i = idx >> 5, dp = idx & 31;
            size_t go = (((size_t)(qt0 + i) * B_ + b) * D_ + h * DH) / 2 + dp;
            __nv_bfloat162 vh = ((const __nv_bfloat162*)Qh)[go];
            __nv_bfloat162 vl = ((const __nv_bfloat162*)Ql)[go];
            ((__nv_bfloat162*)(smc + A3_KH))[i * 36 + dp] = __hmul2(vh, sc);
            ((__nv_bfloat162*)(smc + A3_KL))[i * 36 + dp] = __hmul2(vl, sc);
        }
    }
    __syncthreads();

    uint32_t a_lo = ((lane & 15) * 72 + (lane >> 4) * 8) * 2;
    uint32_t aq[4][4], aql[4][4];
    #pragma unroll
    for (int ks = 0; ks < 4; ks++) {
        ldsm4(aq[ks],  uKh + (wid * 16) * 144 + a_lo + ks * 32);
        ldsm4(aql[ks], uKl + (wid * 16) * 144 + a_lo + ks * 32);
    }
    __syncthreads();

    // K/V chunk loader: 128 s-rows
    auto loadKV = [&](int sch) {
        for (int idx = tid; idx < 1024; idx += 256) {
            int s = idx >> 3, dg = (idx & 7) * 8;
            size_t gk = ((size_t)(sch + s) * B_ + b) * 1024 + h * DH + dg;
            size_t gv = gk + 512;
            uint32_t so = (s * 72 + dg) * 2;
            *(uint4*)(smc + A3_KH + so) = *(const uint4*)(KVh + gk);
            *(uint4*)(smc + A3_KL + so) = *(const uint4*)(KVl + gk);
            *(uint4*)(smc + A3_VH + so) = *(const uint4*)(KVh + gv);
            *(uint4*)(smc + A3_VL + so) = *(const uint4*)(KVl + gv);
        }
    };
    loadKV(0);

    uint32_t b_lo = ((((lane >> 4) & 1) * 8 + (lane & 7)) * 72 + ((lane >> 3) & 1) * 8) * 2;
    uint32_t v_lo = ((lane & 15) * 72 + (lane >> 4) * 8) * 2;

    float oacc[8][4];
    #pragma unroll
    for (int t = 0; t < 8; t++)
        #pragma unroll
        for (int k = 0; k < 4; k++) oacc[t][k] = 0.f;
    float mrA = -1e30f, mrB = -1e30f, lrA = 0.f, lrB = 0.f;

    for (int c = 0; c < 4; c++) {
        __syncthreads();   // KV chunk ready

        #pragma unroll
        for (int half = 0; half < 2; half++) {
            int sb = half * 64;   // sub-chunk base row in smem

            // QK scores over 64 s-rows (8 n8-tiles)
            float cf[8][4];
            #pragma unroll
            for (int st = 0; st < 4; st++) {
                float* c0 = cf[2 * st];
                float* c1 = cf[2 * st + 1];
                #pragma unroll
                for (int k = 0; k < 4; k++) { c0[k] = 0.f; c1[k] = 0.f; }
                uint32_t kb  = uKh + ((sb + st * 16) * 144) + b_lo;
                uint32_t klb = uKl + ((sb + st * 16) * 144) + b_lo;
                #pragma unroll
                for (int ks = 0; ks < 4; ks++) {
                    uint32_t kh[4], kl[4];
                    ldsm4(kh, kb + ks * 32);
                    ldsm4(kl, klb + ks * 32);
                    mma_bf16(c0, aq[ks], kh[0], kh[1]);
                    mma_bf16(c1, aq[ks], kh[2], kh[3]);
                    mma_bf16(c0, aq[ks], kl[0], kl[1]);
                    mma_bf16(c1, aq[ks], kl[2], kl[3]);
                    mma_bf16(c0, aql[ks], kh[0], kh[1]);
                    mma_bf16(c1, aql[ks], kh[2], kh[3]);
                }
            }

            // online softmax update
            float mA = cf[0][0], mB = cf[0][2];
            #pragma unroll
            for (int t = 0; t < 8; t++) {
                mA = fmaxf(mA, fmaxf(cf[t][0], cf[t][1]));
                mB = fmaxf(mB, fmaxf(cf[t][2], cf[t][3]));
            }
            mA = fmaxf(mA, __shfl_xor_sync(0xffffffffu, mA, 1));
            mA = fmaxf(mA, __shfl_xor_sync(0xffffffffu, mA, 2));
            mB = fmaxf(mB, __shfl_xor_sync(0xffffffffu, mB, 1));
            mB = fmaxf(mB, __shfl_xor_sync(0xffffffffu, mB, 2));
            float mnA = fmaxf(mrA, mA), mnB = fmaxf(mrB, mB);
            float alA = __expf(mrA - mnA), alB = __expf(mrB - mnB);
            mrA = mnA; mrB = mnB;
            lrA *= alA; lrB *= alB;
            #pragma unroll
            for (int t = 0; t < 8; t++) {
                oacc[t][0] *= alA; oacc[t][1] *= alA;
                oacc[t][2] *= alB; oacc[t][3] *= alB;
            }
            float sA = 0.f, sB = 0.f;
            #pragma unroll
            for (int t = 0; t < 8; t++) {
                cf[t][0] = __expf(cf[t][0] - mnA);
                cf[t][1] = __expf(cf[t][1] - mnA);
                cf[t][2] = __expf(cf[t][2] - mnB);
                cf[t][3] = __expf(cf[t][3] - mnB);
                sA += cf[t][0] + cf[t][1];
                sB += cf[t][2] + cf[t][3];
            }
            sA += __shfl_xor_sync(0xffffffffu, sA, 1);
            sA += __shfl_xor_sync(0xffffffffu, sA, 2);
            sB += __shfl_xor_sync(0xffffffffu, sB, 1);
            sB += __shfl_xor_sync(0xffffffffu, sB, 2);
            lrA += sA; lrB += sB;

            // pack P into A-frags (hi/lo split in registers)
            uint32_t pah[4][4], pal[4][4];
            #pragma unroll
            for (int j = 0; j < 4; j++) {
                #pragma unroll
                for (int q = 0; q < 2; q++) {
                    float* cc = cf[2 * j + q];
                    __nv_bfloat16 h0, l0, h1, l1;
                    split1(cc[0], h0, l0); split1(cc[1], h1, l1);
                    __nv_bfloat162 vh(h0, h1), vl(l0, l1);
                    pah[j][2 * q]     = *reinterpret_cast<uint32_t*>(&vh);
                    pal[j][2 * q]     = *reinterpret_cast<uint32_t*>(&vl);
                    split1(cc[2], h0, l0); split1(cc[3], h1, l1);
                    __nv_bfloat162 wh2(h0, h1), wl2(l0, l1);
                    pah[j][2 * q + 1] = *reinterpret_cast<uint32_t*>(&wh2);
                    pal[j][2 * q + 1] = *reinterpret_cast<uint32_t*>(&wl2);
                }
            }

            // PV accumulate
            #pragma unroll
            for (int j = 0; j < 4; j++) {
                uint32_t vbase  = uVh + v_lo + (sb + j * 16) * 144;
                uint32_t vlbase = uVl + v_lo + (sb + j * 16) * 144;
                #pragma unroll
                for (int dd = 0; dd < 4; dd++) {
                    uint32_t vh[4], vl[4];
                    ldsm4t(vh, vbase + dd * 32);
                    ldsm4t(vl, vlbase + dd * 32);
                    mma_bf16(oacc[2 * dd],     pah[j], vh[0], vh[1]);
                    mma_bf16(oacc[2 * dd + 1], pah[j], vh[2], vh[3]);
                    mma_bf16(oacc[2 * dd],     pah[j], vl[0], vl[1]);
                    mma_bf16(oacc[2 * dd + 1], pah[j], vl[2], vl[3]);
                    mma_bf16(oacc[2 * dd],     pal[j], vh[0], vh[1]);
                    mma_bf16(oacc[2 * dd + 1], pal[j], vh[2], vh[3]);
                }
            }
        }

        __syncthreads();   // V reads done before overwrite
        if (c < 3) loadKV((c + 1) * 128);
    }

    float invA = 1.0f / lrA, invB = 1.0f / lrB;
    int r0 = lane >> 2, c0 = (lane & 3) * 2;
    int qA = qt0 + wid * 16 + r0;
    #pragma unroll
    for (int t = 0; t < 8; t++) {
        int d = h * DH + t * 8 + c0;
        size_t offA = ((size_t)qA * B_ + b) * D_ + d;
        size_t offB = ((size_t)(qA + 8) * B_ + b) * D_ + d;
        __nv_bfloat16 h0, l0, h1, l1;
        split1(oacc[t][0] * invA, h0, l0); split1(oacc[t][1] * invA, h1, l1);
        *(__nv_bfloat162*)(Oh + offA) = __nv_bfloat162(h0, h1);
        *(__nv_bfloat162*)(Ol + offA) = __nv_bfloat162(l0, l1);
        split1(oacc[t][2] * invB, h0, l0); split1(oacc[t][3] * invB, h1, l1);
        *(__nv_bfloat162*)(Oh + offB) = __nv_bfloat162(h0, h1);
        *(__nv_bfloat162*)(Ol + offB) = __nv_bfloat162(l0, l1);
    }
}

// ---------------- host launcher ----------------
extern "C" void kernel_launch(void* const* d_in, const int* in_sizes, int n_in,
                              void* d_out, int out_size) {
    const float* tgt     = (const float*)d_in[0];
    const float* memory  = (const float*)d_in[1];
    const float* queries = (const float*)d_in[2];
    const float* wk      = (const float*)d_in[3];
    const float* in_w    = (const float*)d_in[4];
    const float* in_b    = (const float*)d_in[5];
    const float* out_w   = (const float*)d_in[6];
    const float* out_b   = (const float*)d_in[7];
    const float* l1w     = (const float*)d_in[8];
    const float* l1b     = (const float*)d_in[9];
    const float* l2w     = (const float*)d_in[10];
    const float* l2b     = (const float*)d_in[11];
    const float* ln1g    = (const float*)d_in[12];
    const float* ln1b    = (const float*)d_in[13];
    const float* ln2g    = (const float*)d_in[14];
    const float* ln2b    = (const float*)d_in[15];
    const float* ln3g    = (const float*)d_in[16];
    const float* ln3b    = (const float*)d_in[17];
    float* out = (float*)d_out;

    float *qa, *x1, *qb, *kv, *tmp, *x2;
    __nv_bfloat16 *x1h, *x1l, *x2h, *x2l, *obh, *obl, *hh, *hl, *memh, *meml, *wh, *wl;
    cudaGetSymbolAddress((void**)&qa,  g_qa);
    cudaGetSymbolAddress((void**)&x1,  g_x1);
    cudaGetSymbolAddress((void**)&qb,  g_q);
    cudaGetSymbolAddress((void**)&kv,  g_kv);
    cudaGetSymbolAddress((void**)&tmp, g_tmp);
    cudaGetSymbolAddress((void**)&x2,  g_x2);
    cudaGetSymbolAddress((void**)&x1h, g_x1h); cudaGetSymbolAddress((void**)&x1l, g_x1l);
    cudaGetSymbolAddress((void**)&x2h, g_x2h); cudaGetSymbolAddress((void**)&x2l, g_x2l);
    cudaGetSymbolAddress((void**)&obh, g_obh); cudaGetSymbolAddress((void**)&obl, g_obl);
    cudaGetSymbolAddress((void**)&hh,  g_hh);  cudaGetSymbolAddress((void**)&hl,  g_hl);
    cudaGetSymbolAddress((void**)&memh, g_memh); cudaGetSymbolAddress((void**)&meml, g_meml);
    cudaGetSymbolAddress((void**)&wh,  g_wh);  cudaGetSymbolAddress((void**)&wl,  g_wl);

    __nv_bfloat16* qh  = (__nv_bfloat16*)qb;
    __nv_bfloat16* ql  = qh + (size_t)T_ * B_ * D_;
    __nv_bfloat16* kvh = (__nv_bfloat16*)kv;
    __nv_bfloat16* kvl = kvh + (size_t)S_ * B_ * 2 * D_;

    cudaFuncSetAttribute(attn4_kernel, cudaFuncAttributeMaxDynamicSharedMemorySize, A3_SMEM);
    cudaFuncSetAttribute(gemm_bf16_v2<0,0>, cudaFuncAttributeMaxDynamicSharedMemorySize, GT_SMEM);
    cudaFuncSetAttribute(gemm_bf16_v2<0,1>, cudaFuncAttributeMaxDynamicSharedMemorySize, GT_SMEM);
    cudaFuncSetAttribute(gemm_bf16_v2<1,1>, cudaFuncAttributeMaxDynamicSharedMemorySize, GT_SMEM);

    const int MR = T_ * B_;

    // ---- fork: side stream runs split_all -> KV-proj; main runs QaN chain then
    //      Q-proj concurrently with KV-proj ----
    cudaStream_t s2;
    cudaEvent_t evFork, evSplit, evKV;
    bool forked = (cudaStreamCreateWithFlags(&s2, cudaStreamNonBlocking) == cudaSuccess);
    if (forked) {
        forked = (cudaEventCreateWithFlags(&evFork,  cudaEventDisableTiming) == cudaSuccess) &&
                 (cudaEventCreateWithFlags(&evSplit, cudaEventDisableTiming) == cudaSuccess) &&
                 (cudaEventCreateWithFlags(&evKV,    cudaEventDisableTiming) == cudaSuccess);
    }

    if (forked) {
        cudaEventRecord(evFork, 0);
        cudaStreamWaitEvent(s2, evFork, 0);

        split_all_kernel<<<5120, 256, 0, s2>>>((const float4*)in_w, (const float4*)out_w,
                                               (const float4*)l1w, (const float4*)l2w,
                                               (const float4*)memory, wh, wl, memh, meml);
        cudaEventRecord(evSplit, s2);
        gemm_bf16_v2<0, 1><<<dim3(8, 32), 512, GT_SMEM, s2>>>(memh, meml,
                                                              wh + WOFF_IN + 512 * 512,
                                                              wl + WOFF_IN + 512 * 512, in_b + 512,
                                                              nullptr, kvh, kvl, S_ * B_, 1024, 512);
        cudaEventRecord(evKV, s2);

        prep_q_kernel<<<NQ_ * H_, 32>>>(queries);
        qa_score_kernel<<<MR / 8, 256>>>(tgt);
        qa_out_kernel<<<B_ * NW, 256>>>(tgt, wk);
        add_ln_kernel<<<MR, 256>>>(tgt, qa, ln1g, ln1b, x1, x1h, x1l, 1);

        cudaStreamWaitEvent(0, evSplit, 0);
        gemm_bf16_v2<0, 1><<<dim3(4, 128), 512, GT_SMEM>>>(x1h, x1l, wh + WOFF_IN, wl + WOFF_IN,
                                                           in_b, nullptr, qh, ql, MR, 512, 512);
        cudaStreamWaitEvent(0, evKV, 0);
    } else {
        split_all_kernel<<<5120, 256>>>((const float4*)in_w, (const float4*)out_w,
                                        (const float4*)l1w, (const float4*)l2w,
                                        (const float4*)memory, wh, wl, memh, meml);
        gemm_bf16_v2<0, 1><<<dim3(8, 32), 512, GT_SMEM>>>(memh, meml, wh + WOFF_IN + 512 * 512,
                                                          wl + WOFF_IN + 512 * 512, in_b + 512,
                                                          nullptr, kvh, kvl, S_ * B_, 1024, 512);
        prep_q_kernel<<<NQ_ * H_, 32>>>(queries);
        qa_score_kernel<<<MR / 8, 256>>>(tgt);
        qa_out_kernel<<<B_ * NW, 256>>>(tgt, wk);
        add_ln_kernel<<<MR, 256>>>(tgt, qa, ln1g, ln1b, x1, x1h, x1l, 1);
        gemm_bf16_v2<0, 1><<<dim3(4, 128), 512, GT_SMEM>>>(x1h, x1l, wh + WOFF_IN, wl + WOFF_IN,
                                                           in_b, nullptr, qh, ql, MR, 512, 512);
    }

    // attention (flash, 128 q-rows per CTA)
    attn4_kernel<<<dim3(T_ / 128, H_, B_), 256, A3_SMEM>>>(qh, ql, kvh, kvl, obh, obl);
    // out proj + LN2
    gemm_bf16_v2<0, 0><<<dim3(4, 128), 512, GT_SMEM>>>(obh, obl, wh + WOFF_OUT, wl + WOFF_OUT,
                                                       out_b, tmp, nullptr, nullptr, MR, 512, 512);
    add_ln_kernel<<<MR, 256>>>(x1, tmp, ln2g, ln2b, x2, x2h, x2l, 0);
    // FFN + LN3
    gemm_bf16_v2<1, 1><<<dim3(16, 128), 512, GT_SMEM>>>(x2h, x2l, wh + WOFF_L1, wl + WOFF_L1,
                                                        l1b, nullptr, hh, hl, MR, DFF_, 512);
    gemm_bf16_v2<0, 0><<<dim3(4, 128), 512, GT_SMEM>>>(hh, hl, wh + WOFF_L2, wl + WOFF_L2,
                                                       l2b, tmp, nullptr, nullptr, MR, 512, DFF_);
    add_ln_kernel<<<MR, 256>>>(x2, tmp, ln3g, ln3b, out, nullptr, nullptr, 0);
    // s2/events intentionally not destroyed: the captured graph references them and
    // kernel_launch only executes at capture time (bounded, no device allocation).
}